// round 2
// baseline (speedup 1.0000x reference)
#include <cuda_runtime.h>
#include <math.h>

// ---------------------------------------------------------------------------
// Scratch: single big __device__ array (no cudaMalloc allowed).
// Layout (floats):
//   GN    [2*768*2048]      @ 0
//   H     [2*2048*768]      @ 3145728
//   Y     [2*2048*768]      @ 6291456
//   Q     [2*2048*768]      @ 9437184
//   K     [2*2048*768]      @ 12582912
//   V     [2*2048*768]      @ 15728640
//   AO    [2*2048*768]      @ 18874368
//   FFIN  [2*768*2048]      @ 22020096
//   FF    [2*3072*2048]     @ 25165824
//   ATTN  [2*12*2048*2048]  @ 37748736
// total = 138412032 floats (= 553.6 MB)
// ---------------------------------------------------------------------------
__device__ float g_scratch[138412032];

#define OFF_GN   0ULL
#define OFF_H    3145728ULL
#define OFF_Y    6291456ULL
#define OFF_Q    9437184ULL
#define OFF_K    12582912ULL
#define OFF_V    15728640ULL
#define OFF_AO   18874368ULL
#define OFF_FFIN 22020096ULL
#define OFF_FF   25165824ULL
#define OFF_ATTN 37748736ULL

// ---------------------------------------------------------------------------
// GroupNorm: x [2,768,2048], 32 groups (24 ch/group), eps 1e-6
// one block per (b, group)
// ---------------------------------------------------------------------------
__global__ __launch_bounds__(256) void groupnorm_k(
    const float* __restrict__ x, const float* __restrict__ scale,
    const float* __restrict__ bias, float* __restrict__ out)
{
    const int CPG = 24, T = 2048;
    int b = blockIdx.x >> 5;
    int g = blockIdx.x & 31;
    const float* xp = x + ((size_t)b * 768 + (size_t)g * CPG) * T;
    float* op = out + ((size_t)b * 768 + (size_t)g * CPG) * T;
    int tid = threadIdx.x;
    const int NEL = CPG * T; // 49152
    float s = 0.f, s2 = 0.f;
    for (int i = tid; i < NEL; i += 256) { float v = xp[i]; s += v; s2 += v * v; }
    __shared__ float r1[256], r2[256];
    r1[tid] = s; r2[tid] = s2; __syncthreads();
    for (int st = 128; st > 0; st >>= 1) {
        if (tid < st) { r1[tid] += r1[tid + st]; r2[tid] += r2[tid + st]; }
        __syncthreads();
    }
    float mu = r1[0] / (float)NEL;
    float var = r2[0] / (float)NEL - mu * mu;
    float rs = rsqrtf(var + 1e-6f);
    for (int i = tid; i < NEL; i += 256) {
        int c = g * CPG + i / T;
        op[i] = (xp[i] - mu) * rs * scale[c] + bias[c];
    }
}

// ---------------------------------------------------------------------------
// LayerNorm over last dim 768, eps 1e-5. One block per token row.
// transpose_out=0: out [row, 768] ; =1: out[((b*768)+i)*2048 + t]  (b=row/2048)
// ---------------------------------------------------------------------------
__global__ __launch_bounds__(256) void layernorm_k(
    const float* __restrict__ in, float* __restrict__ out,
    const float* __restrict__ sc, const float* __restrict__ bi, int transpose_out)
{
    int row = blockIdx.x;
    const float* p = in + (size_t)row * 768;
    int tid = threadIdx.x;
    float v0 = p[tid], v1 = p[tid + 256], v2 = p[tid + 512];
    __shared__ float r1[256], r2[256];
    r1[tid] = v0 + v1 + v2;
    r2[tid] = v0 * v0 + v1 * v1 + v2 * v2;
    __syncthreads();
    for (int st = 128; st > 0; st >>= 1) {
        if (tid < st) { r1[tid] += r1[tid + st]; r2[tid] += r2[tid + st]; }
        __syncthreads();
    }
    float mu = r1[0] * (1.f / 768.f);
    float var = r2[0] * (1.f / 768.f) - mu * mu;
    float rs = rsqrtf(var + 1e-5f);
    float o0 = (v0 - mu) * rs * sc[tid] + bi[tid];
    float o1 = (v1 - mu) * rs * sc[tid + 256] + bi[tid + 256];
    float o2 = (v2 - mu) * rs * sc[tid + 512] + bi[tid + 512];
    if (!transpose_out) {
        float* o = out + (size_t)row * 768;
        o[tid] = o0; o[tid + 256] = o1; o[tid + 512] = o2;
    } else {
        int b = row >> 11, t = row & 2047;
        size_t base = (size_t)b * 768 * 2048 + t;
        out[base + (size_t)tid * 2048] = o0;
        out[base + (size_t)(tid + 256) * 2048] = o1;
        out[base + (size_t)(tid + 512) * 2048] = o2;
    }
}

// ---------------------------------------------------------------------------
// Softmax over rows of width W (W=2048 here). One block per row.
// ---------------------------------------------------------------------------
__global__ __launch_bounds__(256) void softmax_k(float* __restrict__ P, int W)
{
    size_t row = blockIdx.x;
    float* p = P + row * (size_t)W;
    int tid = threadIdx.x;
    __shared__ float red[256];
    float m = -1e30f;
    for (int i = tid; i < W; i += 256) m = fmaxf(m, p[i]);
    red[tid] = m; __syncthreads();
    for (int st = 128; st > 0; st >>= 1) {
        if (tid < st) red[tid] = fmaxf(red[tid], red[tid + st]);
        __syncthreads();
    }
    m = red[0]; __syncthreads();
    float s = 0.f;
    for (int i = tid; i < W; i += 256) { float e = __expf(p[i] - m); p[i] = e; s += e; }
    red[tid] = s; __syncthreads();
    for (int st = 128; st > 0; st >>= 1) {
        if (tid < st) red[tid] += red[tid + st];
        __syncthreads();
    }
    float inv = 1.f / red[0];
    for (int i = tid; i < W; i += 256) p[i] *= inv;
}

// Softmax for width-16 rows: one thread per row.
__global__ __launch_bounds__(256) void softmax16_k(float* __restrict__ P, int rows)
{
    int r = blockIdx.x * 256 + threadIdx.x;
    if (r >= rows) return;
    float* p = P + (size_t)r * 16;
    float m = -1e30f;
    float v[16];
#pragma unroll
    for (int i = 0; i < 16; i++) { v[i] = p[i]; m = fmaxf(m, v[i]); }
    float s = 0.f;
#pragma unroll
    for (int i = 0; i < 16; i++) { v[i] = __expf(v[i] - m); s += v[i]; }
    float inv = 1.f / s;
#pragma unroll
    for (int i = 0; i < 16; i++) p[i] = v[i] * inv;
}

// ---------------------------------------------------------------------------
// Generic batched tiled SGEMM.
//   C[m,n] = alpha * sum_k A[m,k]*B[k|n] + biasM[m] + biasN[n] + Res[m,n]
//   A: A[m*lda + k]            (row-major M x K)
//   B: TRANSB ? B[n*ldb + k] : B[k*ldb + n]
//   C element at C[m*ldCm + n*ldCn]
//   batch z: off = (z/Hdiv)*s?o + (z%Hdiv)*s?i  (same decomposition for A,B,C;
//   Res shares C's offsets)
//   Requires K % 16 == 0, lda,ldb % 4 == 0 (true for every call here).
// ---------------------------------------------------------------------------
template<bool TRANSB>
__global__ __launch_bounds__(256) void gemm_k(
    const float* __restrict__ A, const float* __restrict__ B, float* __restrict__ C,
    const float* __restrict__ biasM, const float* __restrict__ biasN,
    const float* __restrict__ Res,
    int M, int N, int K, int lda, int ldb, int ldCm, int ldCn,
    long long sAo, long long sAi, long long sBo, long long sBi,
    long long sCo, long long sCi, int Hdiv, float alpha)
{
    int z = blockIdx.z;
    int zo = z / Hdiv, zi = z - zo * Hdiv;
    A += (long long)zo * sAo + (long long)zi * sAi;
    B += (long long)zo * sBo + (long long)zi * sBi;
    long long offC = (long long)zo * sCo + (long long)zi * sCi;
    C += offC;
    const float* R = Res ? (Res + offC) : (const float*)0;

    __shared__ float sA[16][64];
    __shared__ float sB[16][64];

    int tid = threadIdx.x;
    int m0 = blockIdx.y * 64;
    int n0 = blockIdx.x * 64;

    int la = tid >> 2;          // 0..63
    int lk = (tid & 3) << 2;    // 0,4,8,12
    int bk = tid >> 4;          // 0..15
    int bn = (tid & 15) << 2;   // 0..60
    int tm = tid >> 4;          // 0..15
    int tn = tid & 15;          // 0..15

    float acc[4][4];
#pragma unroll
    for (int i = 0; i < 4; i++)
#pragma unroll
        for (int j = 0; j < 4; j++) acc[i][j] = 0.f;

    for (int k0 = 0; k0 < K; k0 += 16) {
        float4 av = make_float4(0.f, 0.f, 0.f, 0.f);
        if (m0 + la < M)
            av = *reinterpret_cast<const float4*>(A + (size_t)(m0 + la) * lda + k0 + lk);
        sA[lk + 0][la] = av.x; sA[lk + 1][la] = av.y;
        sA[lk + 2][la] = av.z; sA[lk + 3][la] = av.w;

        if (TRANSB) {
            float4 bv = make_float4(0.f, 0.f, 0.f, 0.f);
            if (n0 + la < N)
                bv = *reinterpret_cast<const float4*>(B + (size_t)(n0 + la) * ldb + k0 + lk);
            sB[lk + 0][la] = bv.x; sB[lk + 1][la] = bv.y;
            sB[lk + 2][la] = bv.z; sB[lk + 3][la] = bv.w;
        } else {
            float4 bv = make_float4(0.f, 0.f, 0.f, 0.f);
            if (n0 + bn + 3 < N) {
                bv = *reinterpret_cast<const float4*>(B + (size_t)(k0 + bk) * ldb + n0 + bn);
            } else if (n0 + bn < N) {
                const float* bp = B + (size_t)(k0 + bk) * ldb;
                bv.x = bp[n0 + bn];
                if (n0 + bn + 1 < N) bv.y = bp[n0 + bn + 1];
                if (n0 + bn + 2 < N) bv.z = bp[n0 + bn + 2];
            }
            sB[bk][bn + 0] = bv.x; sB[bk][bn + 1] = bv.y;
            sB[bk][bn + 2] = bv.z; sB[bk][bn + 3] = bv.w;
        }
        __syncthreads();

#pragma unroll
        for (int k = 0; k < 16; k++) {
            float4 a4 = *reinterpret_cast<const float4*>(&sA[k][tm << 2]);
            float4 b4 = *reinterpret_cast<const float4*>(&sB[k][tn << 2]);
            float ar[4] = {a4.x, a4.y, a4.z, a4.w};
            float br[4] = {b4.x, b4.y, b4.z, b4.w};
#pragma unroll
            for (int i = 0; i < 4; i++)
#pragma unroll
                for (int j = 0; j < 4; j++)
                    acc[i][j] += ar[i] * br[j];
        }
        __syncthreads();
    }

#pragma unroll
    for (int i = 0; i < 4; i++) {
        int m = m0 + (tm << 2) + i;
        if (m >= M) continue;
        float bm = biasM ? biasM[m] : 0.f;
#pragma unroll
        for (int j = 0; j < 4; j++) {
            int n = n0 + (tn << 2) + j;
            if (n >= N) continue;
            float v = acc[i][j] * alpha + bm + (biasN ? biasN[n] : 0.f);
            size_t ci = (size_t)m * ldCm + (size_t)n * ldCn;
            if (R) v += R[ci];
            C[ci] = v;
        }
    }
}

// ---------------------------------------------------------------------------
// Conv1d, K=9, pad=4 over T=2048.  X [B, Cin, T], W [O, Cin, 9].
// Block: 64 O x 128 T tile, thread tile 4x8, cin chunk 8.
// mode 0: Out[b,o,t] = conv + bias
// mode 1: Out[b,o,t] = gelu(conv + bias)                 (exact erf gelu)
// mode 2: Out[((b*T)+t)*O + o] = conv + bias + Res[same] (transpose + residual)
// Requires Cin % 8 == 0, O % 64 == 0.
// ---------------------------------------------------------------------------
__global__ __launch_bounds__(256) void conv1d_k(
    const float* __restrict__ X, const float* __restrict__ W,
    const float* __restrict__ bias, float* __restrict__ Out,
    const float* __restrict__ Res, int Cin, int Oc, int mode)
{
    const int T = 2048;
    int b = blockIdx.z;
    int t0 = blockIdx.x * 128;
    int o0 = blockIdx.y * 64;
    const float* Xb = X + (size_t)b * Cin * T;

    __shared__ float sX[8][136];     // t0-4 .. t0+131
    __shared__ float sW[64 * 72];    // [o][cc][k] flattened

    int tid = threadIdx.x;
    int tm = tid >> 4, tn = tid & 15;
    float acc[4][8];
#pragma unroll
    for (int i = 0; i < 4; i++)
#pragma unroll
        for (int j = 0; j < 8; j++) acc[i][j] = 0.f;

    for (int c0 = 0; c0 < Cin; c0 += 8) {
        for (int i = tid; i < 8 * 136; i += 256) {
            int cc = i / 136, tt = i - cc * 136;
            int tg = t0 + tt - 4;
            sX[cc][tt] = (tg >= 0 && tg < T) ? Xb[(size_t)(c0 + cc) * T + tg] : 0.f;
        }
        const float* Wbase = W + (size_t)o0 * Cin * 9 + (size_t)c0 * 9;
        long long wstride = (long long)Cin * 9;
        for (int i = tid; i < 64 * 72; i += 256) {
            int o = i / 72, r = i - o * 72;
            sW[i] = Wbase[(long long)o * wstride + r];
        }
        __syncthreads();

#pragma unroll
        for (int cc = 0; cc < 8; cc++) {
            float xr[16];
            float4 xv;
            xv = *reinterpret_cast<const float4*>(&sX[cc][tn * 8 + 0]);
            xr[0] = xv.x; xr[1] = xv.y; xr[2] = xv.z; xr[3] = xv.w;
            xv = *reinterpret_cast<const float4*>(&sX[cc][tn * 8 + 4]);
            xr[4] = xv.x; xr[5] = xv.y; xr[6] = xv.z; xr[7] = xv.w;
            xv = *reinterpret_cast<const float4*>(&sX[cc][tn * 8 + 8]);
            xr[8] = xv.x; xr[9] = xv.y; xr[10] = xv.z; xr[11] = xv.w;
            xv = *reinterpret_cast<const float4*>(&sX[cc][tn * 8 + 12]);
            xr[12] = xv.x; xr[13] = xv.y; xr[14] = xv.z; xr[15] = xv.w;
#pragma unroll
            for (int k = 0; k < 9; k++) {
                float wr[4];
#pragma unroll
                for (int i = 0; i < 4; i++)
                    wr[i] = sW[(tm * 4 + i) * 72 + cc * 9 + k];
#pragma unroll
                for (int i = 0; i < 4; i++)
#pragma unroll
                    for (int j = 0; j < 8; j++)
                        acc[i][j] += wr[i] * xr[j + k];
            }
        }
        __syncthreads();
    }

#pragma unroll
    for (int i = 0; i < 4; i++) {
        int o = o0 + tm * 4 + i;
        float bv = bias[o];
#pragma unroll
        for (int j = 0; j < 8; j++) {
            int t = t0 + tn * 8 + j;
            float v = acc[i][j] + bv;
            if (mode == 1) v = 0.5f * v * (1.f + erff(v * 0.70710678118654752f));
            if (mode == 2) {
                size_t idx = ((size_t)b * T + t) * (size_t)Oc + o;
                Out[idx] = v + Res[idx];
            } else {
                size_t idx = ((size_t)b * Oc + o) * T + t;
                Out[idx] = v;
            }
        }
    }
}

// ---------------------------------------------------------------------------
// Host-side launch helper
// ---------------------------------------------------------------------------
static inline void launch_gemm(
    const float* A, const float* B, float* C,
    const float* biasM, const float* biasN, const float* Res,
    int M, int N, int K, int lda, int ldb, int ldCm, int ldCn,
    long long sAo, long long sAi, long long sBo, long long sBi,
    long long sCo, long long sCi, int Hdiv, int batches, float alpha, bool transB)
{
    dim3 grid((N + 63) / 64, (M + 63) / 64, batches);
    if (transB)
        gemm_k<true><<<grid, 256>>>(A, B, C, biasM, biasN, Res, M, N, K,
                                    lda, ldb, ldCm, ldCn,
                                    sAo, sAi, sBo, sBi, sCo, sCi, Hdiv, alpha);
    else
        gemm_k<false><<<grid, 256>>>(A, B, C, biasM, biasN, Res, M, N, K,
                                     lda, ldb, ldCm, ldCn,
                                     sAo, sAi, sBo, sBi, sCo, sCi, Hdiv, alpha);
}

extern "C" void kernel_launch(void* const* d_in, const int* in_sizes, int n_in,
                              void* d_out, int out_size)
{
    const float* x      = (const float*)d_in[0];   // [2,768,2048]
    const float* ctx    = (const float*)d_in[1];   // [2,16,512]
    const float* gn_s   = (const float*)d_in[2];
    const float* gn_b   = (const float*)d_in[3];
    const float* pin_w  = (const float*)d_in[4];   // [768,768]
    const float* pin_b  = (const float*)d_in[5];
    const float* n1_s   = (const float*)d_in[6];   // [2,768]
    const float* n1_b   = (const float*)d_in[7];
    const float* a1_wq  = (const float*)d_in[8];   // [2,768,768]
    const float* a1_wk  = (const float*)d_in[9];
    const float* a1_wv  = (const float*)d_in[10];
    const float* a1_wo  = (const float*)d_in[11];
    const float* a1_bo  = (const float*)d_in[12];  // [2,768]
    const float* n2_s   = (const float*)d_in[13];
    const float* n2_b   = (const float*)d_in[14];
    const float* a2_wq  = (const float*)d_in[15];  // [2,768,768]
    const float* a2_wk  = (const float*)d_in[16];  // [2,512,768]
    const float* a2_wv  = (const float*)d_in[17];  // [2,512,768]
    const float* a2_wo  = (const float*)d_in[18];  // [2,768,768]
    const float* a2_bo  = (const float*)d_in[19];
    const float* n3_s   = (const float*)d_in[20];
    const float* n3_b   = (const float*)d_in[21];
    const float* ff1_w  = (const float*)d_in[22];  // [2,3072,768,9]
    const float* ff1_b  = (const float*)d_in[23];  // [2,3072]
    const float* ff2_w  = (const float*)d_in[24];  // [2,768,3072,9]
    const float* ff2_b  = (const float*)d_in[25];  // [2,768]
    const float* pout_w = (const float*)d_in[26];  // [768,768]
    const float* pout_b = (const float*)d_in[27];
    float* out = (float*)d_out;                    // [2,768,2048]

    float* S = 0;
    cudaGetSymbolAddress((void**)&S, g_scratch);
    float* GN   = S + OFF_GN;
    float* Hbuf = S + OFF_H;
    float* Y    = S + OFF_Y;
    float* Q    = S + OFF_Q;
    float* Kb   = S + OFF_K;
    float* V    = S + OFF_V;
    float* AO   = S + OFF_AO;
    float* FFIN = S + OFF_FFIN;
    float* FF   = S + OFF_FF;
    float* ATTN = S + OFF_ATTN;

    const long long NI = 2048LL * 768;     // per-batch token block
    const long long NN = 2048LL * 2048;    // per-head score block (self)
    const long long CT = 768LL * 2048;

    // 1. GroupNorm
    groupnorm_k<<<64, 256>>>(x, gn_s, gn_b, GN);

    // 2. proj_in: per b:  h[b,t,o] = sum_c pin_w[o,c] * GN[b,c,t] + pin_b[o]
    //    GEMM NN with M=o, N=t; C written transposed into [b,t,o].
    launch_gemm(pin_w, GN, Hbuf, pin_b, 0, 0,
                768, 2048, 768, 768, 2048, /*ldCm*/1, /*ldCn*/768,
                0, 0, CT, 0, NI, 0, 1, 2, 1.f, false);

    for (int d = 0; d < 2; d++) {
        const float* wq1 = a1_wq + (size_t)d * 768 * 768;
        const float* wk1 = a1_wk + (size_t)d * 768 * 768;
        const float* wv1 = a1_wv + (size_t)d * 768 * 768;
        const float* wo1 = a1_wo + (size_t)d * 768 * 768;
        const float* wq2 = a2_wq + (size_t)d * 768 * 768;
        const float* wk2 = a2_wk + (size_t)d * 512 * 768;
        const float* wv2 = a2_wv + (size_t)d * 512 * 768;
        const float* wo2 = a2_wo + (size_t)d * 768 * 768;

        // ---- self-attention ----
        layernorm_k<<<4096, 256>>>(Hbuf, Y, n1_s + d * 768, n1_b + d * 768, 0);
        launch_gemm(Y, wq1, Q, 0, 0, 0, 4096, 768, 768, 768, 768, 768, 1,
                    0, 0, 0, 0, 0, 0, 1, 1, 1.f, false);
        launch_gemm(Y, wk1, Kb, 0, 0, 0, 4096, 768, 768, 768, 768, 768, 1,
                    0, 0, 0, 0, 0, 0, 1, 1, 1.f, false);
        launch_gemm(Y, wv1, V, 0, 0, 0, 4096, 768, 768, 768, 768, 768, 1,
                    0, 0, 0, 0, 0, 0, 1, 1, 1.f, false);
        // scores[b,h,i,j] = 0.125 * q . k   (z = b*12+h)
        launch_gemm(Q, Kb, ATTN, 0, 0, 0, 2048, 2048, 64, 768, 768, 2048, 1,
                    NI, 64, NI, 64, 12 * NN, NN, 12, 24, 0.125f, true);
        softmax_k<<<49152, 256>>>(ATTN, 2048);
        // out[b,i,h,:] = attn @ v
        launch_gemm(ATTN, V, AO, 0, 0, 0, 2048, 64, 2048, 2048, 768, 768, 1,
                    12 * NN, NN, NI, 64, NI, 64, 12, 24, 1.f, false);
        // o-proj + bias + residual
        launch_gemm(AO, wo1, Hbuf, 0, a1_bo + d * 768, Hbuf,
                    4096, 768, 768, 768, 768, 768, 1,
                    0, 0, 0, 0, 0, 0, 1, 1, 1.f, false);

        // ---- cross-attention ----
        layernorm_k<<<4096, 256>>>(Hbuf, Y, n2_s + d * 768, n2_b + d * 768, 0);
        launch_gemm(Y, wq2, Q, 0, 0, 0, 4096, 768, 768, 768, 768, 768, 1,
                    0, 0, 0, 0, 0, 0, 1, 1, 1.f, false);
        // k2/v2: context [b,16,512] @ w [512,768] -> [b,16,768]
        launch_gemm(ctx, wk2, Kb, 0, 0, 0, 16, 768, 512, 512, 768, 768, 1,
                    16LL * 512, 0, 0, 0, 16LL * 768, 0, 1, 2, 1.f, false);
        launch_gemm(ctx, wv2, V, 0, 0, 0, 16, 768, 512, 512, 768, 768, 1,
                    16LL * 512, 0, 0, 0, 16LL * 768, 0, 1, 2, 1.f, false);
        // scores2 [z,2048,16]
        launch_gemm(Q, Kb, ATTN, 0, 0, 0, 2048, 16, 64, 768, 768, 16, 1,
                    NI, 64, 16LL * 768, 64, 12LL * 2048 * 16, 2048LL * 16,
                    12, 24, 0.125f, true);
        softmax16_k<<<(49152 + 255) / 256, 256>>>(ATTN, 49152);
        launch_gemm(ATTN, V, AO, 0, 0, 0, 2048, 64, 16, 16, 768, 768, 1,
                    12LL * 2048 * 16, 2048LL * 16, 16LL * 768, 64, NI, 64,
                    12, 24, 1.f, false);
        launch_gemm(AO, wo2, Hbuf, 0, a2_bo + d * 768, Hbuf,
                    4096, 768, 768, 768, 768, 768, 1,
                    0, 0, 0, 0, 0, 0, 1, 1, 1.f, false);

        // ---- conv feed-forward ----
        layernorm_k<<<4096, 256>>>(Hbuf, FFIN, n3_s + d * 768, n3_b + d * 768, 1);
        conv1d_k<<<dim3(16, 48, 2), 256>>>(FFIN, ff1_w + (size_t)d * 3072 * 768 * 9,
                                           ff1_b + (size_t)d * 3072, FF, 0,
                                           768, 3072, 1);
        conv1d_k<<<dim3(16, 12, 2), 256>>>(FF, ff2_w + (size_t)d * 768 * 3072 * 9,
                                           ff2_b + (size_t)d * 768, Hbuf, Hbuf,
                                           3072, 768, 2);
    }

    // proj_out: out[b,o,t] = sum_i pout_w[o,i]*h[b,t,i] + pout_b[o] + x[b,o,t]
    launch_gemm(pout_w, Hbuf, out, pout_b, 0, x,
                768, 2048, 768, 768, 768, /*ldCm*/2048, /*ldCn*/1,
                0, 0, NI, 0, CT, 0, 1, 2, 1.f, true);
}

// round 9
// speedup vs baseline: 1.3556x; 1.3556x over previous
#include <cuda_runtime.h>
#include <cuda_bf16.h>
#include <math.h>
#include <stdint.h>

using bf16 = __nv_bfloat16;

// ---------------------------------------------------------------------------
// Scratch (no cudaMalloc). fp32 part (same layout as R2) + bf16 part.
// ---------------------------------------------------------------------------
__device__ float g_scratch[138412032];
#define OFF_GN   0ULL
#define OFF_H    3145728ULL
#define OFF_Y    6291456ULL
#define OFF_Q    9437184ULL
#define OFF_K    12582912ULL
#define OFF_V    15728640ULL
#define OFF_AO   18874368ULL
#define OFF_ATTN 37748736ULL

__device__ __align__(16) bf16 g_bf[73924608];
#define BOFF_FFINH 0ULL
#define BOFF_FFINL 3145728ULL
#define BOFF_FFH   6291456ULL
#define BOFF_FFL   18874368ULL
#define BOFF_WTH   31457280ULL
#define BOFF_WTL   52690944ULL

// ---------------------------------------------------------------------------
// GroupNorm: x [2,768,2048], 32 groups, eps 1e-6
// ---------------------------------------------------------------------------
__global__ __launch_bounds__(256) void groupnorm_k(
    const float* __restrict__ x, const float* __restrict__ scale,
    const float* __restrict__ bias, float* __restrict__ out)
{
    const int CPG = 24, T = 2048;
    int b = blockIdx.x >> 5;
    int g = blockIdx.x & 31;
    const float* xp = x + ((size_t)b * 768 + (size_t)g * CPG) * T;
    float* op = out + ((size_t)b * 768 + (size_t)g * CPG) * T;
    int tid = threadIdx.x;
    const int NEL = CPG * T;
    float s = 0.f, s2 = 0.f;
    for (int i = tid; i < NEL; i += 256) { float v = xp[i]; s += v; s2 += v * v; }
    __shared__ float r1[256], r2[256];
    r1[tid] = s; r2[tid] = s2; __syncthreads();
    for (int st = 128; st > 0; st >>= 1) {
        if (tid < st) { r1[tid] += r1[tid + st]; r2[tid] += r2[tid + st]; }
        __syncthreads();
    }
    float mu = r1[0] / (float)NEL;
    float var = r2[0] / (float)NEL - mu * mu;
    float rs = rsqrtf(var + 1e-6f);
    for (int i = tid; i < NEL; i += 256) {
        int c = g * CPG + i / T;
        op[i] = (xp[i] - mu) * rs * scale[c] + bias[c];
    }
}

// ---------------------------------------------------------------------------
// LayerNorm -> fp32 rows (attention inputs)
// ---------------------------------------------------------------------------
__global__ __launch_bounds__(256) void layernorm_k(
    const float* __restrict__ in, float* __restrict__ out,
    const float* __restrict__ sc, const float* __restrict__ bi)
{
    int row = blockIdx.x;
    const float* p = in + (size_t)row * 768;
    int tid = threadIdx.x;
    float v0 = p[tid], v1 = p[tid + 256], v2 = p[tid + 512];
    __shared__ float r1[256], r2[256];
    r1[tid] = v0 + v1 + v2;
    r2[tid] = v0 * v0 + v1 * v1 + v2 * v2;
    __syncthreads();
    for (int st = 128; st > 0; st >>= 1) {
        if (tid < st) { r1[tid] += r1[tid + st]; r2[tid] += r2[tid + st]; }
        __syncthreads();
    }
    float mu = r1[0] * (1.f / 768.f);
    float var = r2[0] * (1.f / 768.f) - mu * mu;
    float rs = rsqrtf(var + 1e-5f);
    float* o = out + (size_t)row * 768;
    o[tid]       = (v0 - mu) * rs * sc[tid] + bi[tid];
    o[tid + 256] = (v1 - mu) * rs * sc[tid + 256] + bi[tid + 256];
    o[tid + 512] = (v2 - mu) * rs * sc[tid + 512] + bi[tid + 512];
}

// LayerNorm -> transposed bf16 hi/lo [b, c, t] (conv-FFN input)
__global__ __launch_bounds__(256) void layernorm_bf_k(
    const float* __restrict__ in, bf16* __restrict__ outh, bf16* __restrict__ outl,
    const float* __restrict__ sc, const float* __restrict__ bi)
{
    int row = blockIdx.x;
    const float* p = in + (size_t)row * 768;
    int tid = threadIdx.x;
    float v0 = p[tid], v1 = p[tid + 256], v2 = p[tid + 512];
    __shared__ float r1[256], r2[256];
    r1[tid] = v0 + v1 + v2;
    r2[tid] = v0 * v0 + v1 * v1 + v2 * v2;
    __syncthreads();
    for (int st = 128; st > 0; st >>= 1) {
        if (tid < st) { r1[tid] += r1[tid + st]; r2[tid] += r2[tid + st]; }
        __syncthreads();
    }
    float mu = r1[0] * (1.f / 768.f);
    float var = r2[0] * (1.f / 768.f) - mu * mu;
    float rs = rsqrtf(var + 1e-5f);
    int b = row >> 11, t = row & 2047;
    size_t base = (size_t)b * 768 * 2048 + t;
    float ov[3] = { (v0 - mu) * rs * sc[tid] + bi[tid],
                    (v1 - mu) * rs * sc[tid + 256] + bi[tid + 256],
                    (v2 - mu) * rs * sc[tid + 512] + bi[tid + 512] };
#pragma unroll
    for (int j = 0; j < 3; j++) {
        size_t idx = base + (size_t)(tid + 256 * j) * 2048;
        bf16 h = __float2bfloat16(ov[j]);
        outh[idx] = h;
        outl[idx] = __float2bfloat16(ov[j] - __bfloat162float(h));
    }
}

// ---------------------------------------------------------------------------
// Softmax
// ---------------------------------------------------------------------------
__global__ __launch_bounds__(256) void softmax_k(float* __restrict__ P, int W)
{
    size_t row = blockIdx.x;
    float* p = P + row * (size_t)W;
    int tid = threadIdx.x;
    __shared__ float red[256];
    float m = -1e30f;
    for (int i = tid; i < W; i += 256) m = fmaxf(m, p[i]);
    red[tid] = m; __syncthreads();
    for (int st = 128; st > 0; st >>= 1) {
        if (tid < st) red[tid] = fmaxf(red[tid], red[tid + st]);
        __syncthreads();
    }
    m = red[0]; __syncthreads();
    float s = 0.f;
    for (int i = tid; i < W; i += 256) { float e = __expf(p[i] - m); p[i] = e; s += e; }
    red[tid] = s; __syncthreads();
    for (int st = 128; st > 0; st >>= 1) {
        if (tid < st) red[tid] += red[tid + st];
        __syncthreads();
    }
    float inv = 1.f / red[0];
    for (int i = tid; i < W; i += 256) p[i] *= inv;
}

__global__ __launch_bounds__(256) void softmax16_k(float* __restrict__ P, int rows)
{
    int r = blockIdx.x * 256 + threadIdx.x;
    if (r >= rows) return;
    float* p = P + (size_t)r * 16;
    float m = -1e30f;
    float v[16];
#pragma unroll
    for (int i = 0; i < 16; i++) { v[i] = p[i]; m = fmaxf(m, v[i]); }
    float s = 0.f;
#pragma unroll
    for (int i = 0; i < 16; i++) { v[i] = __expf(v[i] - m); s += v[i]; }
    float inv = 1.f / s;
#pragma unroll
    for (int i = 0; i < 16; i++) p[i] = v[i] * inv;
}

// ---------------------------------------------------------------------------
// Generic batched tiled SGEMM (proven in R2)
// ---------------------------------------------------------------------------
template<bool TRANSB>
__global__ __launch_bounds__(256) void gemm_k(
    const float* __restrict__ A, const float* __restrict__ B, float* __restrict__ C,
    const float* __restrict__ biasM, const float* __restrict__ biasN,
    const float* __restrict__ Res,
    int M, int N, int K, int lda, int ldb, int ldCm, int ldCn,
    long long sAo, long long sAi, long long sBo, long long sBi,
    long long sCo, long long sCi, int Hdiv, float alpha)
{
    int z = blockIdx.z;
    int zo = z / Hdiv, zi = z - zo * Hdiv;
    A += (long long)zo * sAo + (long long)zi * sAi;
    B += (long long)zo * sBo + (long long)zi * sBi;
    long long offC = (long long)zo * sCo + (long long)zi * sCi;
    C += offC;
    const float* R = Res ? (Res + offC) : (const float*)0;

    __shared__ float sA[16][64];
    __shared__ float sB[16][64];

    int tid = threadIdx.x;
    int m0 = blockIdx.y * 64;
    int n0 = blockIdx.x * 64;

    int la = tid >> 2;
    int lk = (tid & 3) << 2;
    int bk = tid >> 4;
    int bn = (tid & 15) << 2;
    int tm = tid >> 4;
    int tn = tid & 15;

    float acc[4][4];
#pragma unroll
    for (int i = 0; i < 4; i++)
#pragma unroll
        for (int j = 0; j < 4; j++) acc[i][j] = 0.f;

    for (int k0 = 0; k0 < K; k0 += 16) {
        float4 av = make_float4(0.f, 0.f, 0.f, 0.f);
        if (m0 + la < M)
            av = *reinterpret_cast<const float4*>(A + (size_t)(m0 + la) * lda + k0 + lk);
        sA[lk + 0][la] = av.x; sA[lk + 1][la] = av.y;
        sA[lk + 2][la] = av.z; sA[lk + 3][la] = av.w;

        if (TRANSB) {
            float4 bv = make_float4(0.f, 0.f, 0.f, 0.f);
            if (n0 + la < N)
                bv = *reinterpret_cast<const float4*>(B + (size_t)(n0 + la) * ldb + k0 + lk);
            sB[lk + 0][la] = bv.x; sB[lk + 1][la] = bv.y;
            sB[lk + 2][la] = bv.z; sB[lk + 3][la] = bv.w;
        } else {
            float4 bv = make_float4(0.f, 0.f, 0.f, 0.f);
            if (n0 + bn + 3 < N) {
                bv = *reinterpret_cast<const float4*>(B + (size_t)(k0 + bk) * ldb + n0 + bn);
            } else if (n0 + bn < N) {
                const float* bp = B + (size_t)(k0 + bk) * ldb;
                bv.x = bp[n0 + bn];
                if (n0 + bn + 1 < N) bv.y = bp[n0 + bn + 1];
                if (n0 + bn + 2 < N) bv.z = bp[n0 + bn + 2];
            }
            sB[bk][bn + 0] = bv.x; sB[bk][bn + 1] = bv.y;
            sB[bk][bn + 2] = bv.z; sB[bk][bn + 3] = bv.w;
        }
        __syncthreads();

#pragma unroll
        for (int k = 0; k < 16; k++) {
            float4 a4 = *reinterpret_cast<const float4*>(&sA[k][tm << 2]);
            float4 b4 = *reinterpret_cast<const float4*>(&sB[k][tn << 2]);
            float ar[4] = {a4.x, a4.y, a4.z, a4.w};
            float br[4] = {b4.x, b4.y, b4.z, b4.w};
#pragma unroll
            for (int i = 0; i < 4; i++)
#pragma unroll
                for (int j = 0; j < 4; j++)
                    acc[i][j] += ar[i] * br[j];
        }
        __syncthreads();
    }

#pragma unroll
    for (int i = 0; i < 4; i++) {
        int m = m0 + (tm << 2) + i;
        if (m >= M) continue;
        float bm = biasM ? biasM[m] : 0.f;
#pragma unroll
        for (int j = 0; j < 4; j++) {
            int n = n0 + (tn << 2) + j;
            if (n >= N) continue;
            float v = acc[i][j] * alpha + bm + (biasN ? biasN[n] : 0.f);
            size_t ci = (size_t)m * ldCm + (size_t)n * ldCn;
            if (R) v += R[ci];
            C[ci] = v;
        }
    }
}

static inline void launch_gemm(
    const float* A, const float* B, float* C,
    const float* biasM, const float* biasN, const float* Res,
    int M, int N, int K, int lda, int ldb, int ldCm, int ldCn,
    long long sAo, long long sAi, long long sBo, long long sBi,
    long long sCo, long long sCi, int Hdiv, int batches, float alpha, bool transB)
{
    dim3 grid((N + 63) / 64, (M + 63) / 64, batches);
    if (transB)
        gemm_k<true><<<grid, 256>>>(A, B, C, biasM, biasN, Res, M, N, K,
                                    lda, ldb, ldCm, ldCn,
                                    sAo, sAi, sBo, sBi, sCo, sCi, Hdiv, alpha);
    else
        gemm_k<false><<<grid, 256>>>(A, B, C, biasM, biasN, Res, M, N, K,
                                     lda, ldb, ldCm, ldCn,
                                     sAo, sAi, sBo, sBi, sCo, sCi, Hdiv, alpha);
}

// ---------------------------------------------------------------------------
// Weight permute+split: W [O][C][9] f32 -> Wh/Wl [(c/16)][o][9][c%16] bf16
// ---------------------------------------------------------------------------
__global__ __launch_bounds__(256) void wperm_k(
    const float* __restrict__ W, bf16* __restrict__ Wh, bf16* __restrict__ Wl,
    int O, int C)
{
    long long n = (long long)O * C * 9;
    for (long long i = (long long)blockIdx.x * 256 + threadIdx.x; i < n;
         i += (long long)gridDim.x * 256) {
        int k = (int)(i % 9);
        long long oc = i / 9;
        int c = (int)(oc % C);
        int o = (int)(oc / C);
        float w = W[i];
        bf16 h = __float2bfloat16(w);
        bf16 l = __float2bfloat16(w - __bfloat162float(h));
        long long dst = (((long long)(c >> 4) * O + o) * 9 + k) * 16 + (c & 15);
        Wh[dst] = h; Wl[dst] = l;
    }
}

// ---------------------------------------------------------------------------
// Tensor-core conv1d (K=9, pad=4, T=2048) via mma.sync m16n8k16 bf16x3.
// Block tile 64o x 64t; 8 warps = 2(warp_o) x 4(warp_t); warp tile 32o x 16t.
// GELU=1: Out = gelu(conv+bias) -> bf16 hi/lo [B,Oc,T]
// GELU=0: Out = conv+bias+Res   -> fp32 [(b*T+t)*Oc+o]
// ---------------------------------------------------------------------------
__device__ __forceinline__ void mma16816(float* c, const uint32_t* a,
                                         uint32_t b0, uint32_t b1) {
    asm volatile(
        "mma.sync.aligned.m16n8k16.row.col.f32.bf16.bf16.f32 "
        "{%0,%1,%2,%3}, {%4,%5,%6,%7}, {%8,%9}, {%0,%1,%2,%3};"
        : "+f"(c[0]), "+f"(c[1]), "+f"(c[2]), "+f"(c[3])
        : "r"(a[0]), "r"(a[1]), "r"(a[2]), "r"(a[3]), "r"(b0), "r"(b1));
}

template<int GELU>
__global__ __launch_bounds__(256) void convmma_k(
    const bf16* __restrict__ Xh, const bf16* __restrict__ Xl,
    const bf16* __restrict__ Wh, const bf16* __restrict__ Wl,
    const float* __restrict__ bias, int Cin, int Oc,
    bf16* __restrict__ Oh, bf16* __restrict__ Ol,
    float* __restrict__ Of, const float* __restrict__ Res)
{
    const int T = 2048;
    __shared__ bf16 sW[2][64 * 144];   // [comp][o*144 + k*16 + c]
    __shared__ bf16 sX[2][72 * 18];    // [comp][t*18 + c], t in [t0-4, t0+67]

    int b = blockIdx.z, t0 = blockIdx.x * 64, o0 = blockIdx.y * 64;
    int tid = threadIdx.x, wid = tid >> 5, lane = tid & 31;
    int g = lane >> 2, tig = lane & 3;
    int warp_o = wid >> 2, warp_t = wid & 3;

    float acc[2][2][4];
#pragma unroll
    for (int mt = 0; mt < 2; mt++)
#pragma unroll
        for (int nt = 0; nt < 2; nt++)
#pragma unroll
            for (int i = 0; i < 4; i++) acc[mt][nt][i] = 0.f;

    const bf16* Xhb = Xh + (long long)b * Cin * T;
    const bf16* Xlb = Xl + (long long)b * Cin * T;

    for (int c0 = 0; c0 < Cin; c0 += 16) {
        {
            const uint4* sh = (const uint4*)(Wh + ((long long)(c0 >> 4) * Oc + o0) * 144);
            const uint4* sl = (const uint4*)(Wl + ((long long)(c0 >> 4) * Oc + o0) * 144);
            uint4* dh = (uint4*)sW[0];
            uint4* dl = (uint4*)sW[1];
            for (int i = tid; i < 64 * 144 / 8; i += 256) { dh[i] = sh[i]; dl[i] = sl[i]; }
        }
        for (int i = tid; i < 16 * 72; i += 256) {
            int c = i / 72, t = i - c * 72;
            int tg = t0 + t - 4;
            bf16 vh = __float2bfloat16(0.f), vl = vh;
            if (tg >= 0 && tg < T) {
                long long gi = (long long)(c0 + c) * T + tg;
                vh = Xhb[gi]; vl = Xlb[gi];
            }
            sX[0][t * 18 + c] = vh;
            sX[1][t * 18 + c] = vl;
        }
        __syncthreads();

#pragma unroll
        for (int shift = 0; shift < 9; shift++) {
            uint32_t ah[2][4], al[2][4];
#pragma unroll
            for (int mt = 0; mt < 2; mt++) {
                int orow = warp_o * 32 + mt * 16 + g;
                int base = orow * 144 + shift * 16 + 2 * tig;
                ah[mt][0] = *(const uint32_t*)&sW[0][base];
                ah[mt][1] = *(const uint32_t*)&sW[0][base + 8 * 144];
                ah[mt][2] = *(const uint32_t*)&sW[0][base + 8];
                ah[mt][3] = *(const uint32_t*)&sW[0][base + 8 * 144 + 8];
                al[mt][0] = *(const uint32_t*)&sW[1][base];
                al[mt][1] = *(const uint32_t*)&sW[1][base + 8 * 144];
                al[mt][2] = *(const uint32_t*)&sW[1][base + 8];
                al[mt][3] = *(const uint32_t*)&sW[1][base + 8 * 144 + 8];
            }
#pragma unroll
            for (int nt = 0; nt < 2; nt++) {
                int tp = warp_t * 16 + nt * 8 + g + shift;
                uint32_t bh0 = *(const uint32_t*)&sX[0][tp * 18 + 2 * tig];
                uint32_t bh1 = *(const uint32_t*)&sX[0][tp * 18 + 2 * tig + 8];
                uint32_t bl0 = *(const uint32_t*)&sX[1][tp * 18 + 2 * tig];
                uint32_t bl1 = *(const uint32_t*)&sX[1][tp * 18 + 2 * tig + 8];
#pragma unroll
                for (int mt = 0; mt < 2; mt++) {
                    mma16816(acc[mt][nt], ah[mt], bh0, bh1);
                    mma16816(acc[mt][nt], al[mt], bh0, bh1);
                    mma16816(acc[mt][nt], ah[mt], bl0, bl1);
                }
            }
        }
        __syncthreads();
    }

#pragma unroll
    for (int mt = 0; mt < 2; mt++) {
        int o_lo = o0 + warp_o * 32 + mt * 16 + g;
        int o_hi = o_lo + 8;
        float b_lo = bias[o_lo], b_hi = bias[o_hi];
#pragma unroll
        for (int nt = 0; nt < 2; nt++) {
            int t = t0 + warp_t * 16 + nt * 8 + 2 * tig;
            float v00 = acc[mt][nt][0] + b_lo;
            float v01 = acc[mt][nt][1] + b_lo;
            float v10 = acc[mt][nt][2] + b_hi;
            float v11 = acc[mt][nt][3] + b_hi;
            if (GELU) {
                v00 = 0.5f * v00 * (1.f + erff(v00 * 0.70710678118654752f));
                v01 = 0.5f * v01 * (1.f + erff(v01 * 0.70710678118654752f));
                v10 = 0.5f * v10 * (1.f + erff(v10 * 0.70710678118654752f));
                v11 = 0.5f * v11 * (1.f + erff(v11 * 0.70710678118654752f));
                bf16 h00 = __float2bfloat16(v00), h01 = __float2bfloat16(v01);
                bf16 h10 = __float2bfloat16(v10), h11 = __float2bfloat16(v11);
                __nv_bfloat162 ph0, ph1, pl0, pl1;
                ph0.x = h00; ph0.y = h01;
                ph1.x = h10; ph1.y = h11;
                pl0.x = __float2bfloat16(v00 - __bfloat162float(h00));
                pl0.y = __float2bfloat16(v01 - __bfloat162float(h01));
                pl1.x = __float2bfloat16(v10 - __bfloat162float(h10));
                pl1.y = __float2bfloat16(v11 - __bfloat162float(h11));
                long long i0 = ((long long)b * Oc + o_lo) * T + t;
                long long i1 = ((long long)b * Oc + o_hi) * T + t;
                *(__nv_bfloat162*)&Oh[i0] = ph0;
                *(__nv_bfloat162*)&Oh[i1] = ph1;
                *(__nv_bfloat162*)&Ol[i0] = pl0;
                *(__nv_bfloat162*)&Ol[i1] = pl1;
            } else {
                long long r00 = ((long long)b * T + t) * Oc + o_lo;
                long long r01 = ((long long)b * T + t + 1) * Oc + o_lo;
                long long r10 = ((long long)b * T + t) * Oc + o_hi;
                long long r11 = ((long long)b * T + t + 1) * Oc + o_hi;
                Of[r00] = v00 + Res[r00];
                Of[r01] = v01 + Res[r01];
                Of[r10] = v10 + Res[r10];
                Of[r11] = v11 + Res[r11];
            }
        }
    }
}

// ---------------------------------------------------------------------------
extern "C" void kernel_launch(void* const* d_in, const int* in_sizes, int n_in,
                              void* d_out, int out_size)
{
    const float* x      = (const float*)d_in[0];
    const float* ctx    = (const float*)d_in[1];
    const float* gn_s   = (const float*)d_in[2];
    const float* gn_b   = (const float*)d_in[3];
    const float* pin_w  = (const float*)d_in[4];
    const float* pin_b  = (const float*)d_in[5];
    const float* n1_s   = (const float*)d_in[6];
    const float* n1_b   = (const float*)d_in[7];
    const float* a1_wq  = (const float*)d_in[8];
    const float* a1_wk  = (const float*)d_in[9];
    const float* a1_wv  = (const float*)d_in[10];
    const float* a1_wo  = (const float*)d_in[11];
    const float* a1_bo  = (const float*)d_in[12];
    const float* n2_s   = (const float*)d_in[13];
    const float* n2_b   = (const float*)d_in[14];
    const float* a2_wq  = (const float*)d_in[15];
    const float* a2_wk  = (const float*)d_in[16];
    const float* a2_wv  = (const float*)d_in[17];
    const float* a2_wo  = (const float*)d_in[18];
    const float* a2_bo  = (const float*)d_in[19];
    const float* n3_s   = (const float*)d_in[20];
    const float* n3_b   = (const float*)d_in[21];
    const float* ff1_w  = (const float*)d_in[22];
    const float* ff1_b  = (const float*)d_in[23];
    const float* ff2_w  = (const float*)d_in[24];
    const float* ff2_b  = (const float*)d_in[25];
    const float* pout_w = (const float*)d_in[26];
    const float* pout_b = (const float*)d_in[27];
    float* out = (float*)d_out;

    float* S = 0;
    cudaGetSymbolAddress((void**)&S, g_scratch);
    bf16* SB = 0;
    cudaGetSymbolAddress((void**)&SB, g_bf);

    float* GN   = S + OFF_GN;
    float* Hbuf = S + OFF_H;
    float* Y    = S + OFF_Y;
    float* Q    = S + OFF_Q;
    float* Kb   = S + OFF_K;
    float* V    = S + OFF_V;
    float* AO   = S + OFF_AO;
    float* ATTN = S + OFF_ATTN;
    bf16* FFINh = SB + BOFF_FFINH;
    bf16* FFINl = SB + BOFF_FFINL;
    bf16* FFh   = SB + BOFF_FFH;
    bf16* FFl   = SB + BOFF_FFL;
    bf16* Wth   = SB + BOFF_WTH;
    bf16* Wtl   = SB + BOFF_WTL;

    const long long NI = 2048LL * 768;
    const long long NN = 2048LL * 2048;
    const long long CT = 768LL * 2048;

    groupnorm_k<<<64, 256>>>(x, gn_s, gn_b, GN);
    launch_gemm(pin_w, GN, Hbuf, pin_b, 0, 0,
                768, 2048, 768, 768, 2048, 1, 768,
                0, 0, CT, 0, NI, 0, 1, 2, 1.f, false);

    for (int d = 0; d < 2; d++) {
        const float* wq1 = a1_wq + (size_t)d * 768 * 768;
        const float* wk1 = a1_wk + (size_t)d * 768 * 768;
        const float* wv1 = a1_wv + (size_t)d * 768 * 768;
        const float* wo1 = a1_wo + (size_t)d * 768 * 768;
        const float* wq2 = a2_wq + (size_t)d * 768 * 768;
        const float* wk2 = a2_wk + (size_t)d * 512 * 768;
        const float* wv2 = a2_wv + (size_t)d * 512 * 768;
        const float* wo2 = a2_wo + (size_t)d * 768 * 768;

        // ---- self-attention ----
        layernorm_k<<<4096, 256>>>(Hbuf, Y, n1_s + d * 768, n1_b + d * 768);
        launch_gemm(Y, wq1, Q, 0, 0, 0, 4096, 768, 768, 768, 768, 768, 1,
                    0, 0, 0, 0, 0, 0, 1, 1, 1.f, false);
        launch_gemm(Y, wk1, Kb, 0, 0, 0, 4096, 768, 768, 768, 768, 768, 1,
                    0, 0, 0, 0, 0, 0, 1, 1, 1.f, false);
        launch_gemm(Y, wv1, V, 0, 0, 0, 4096, 768, 768, 768, 768, 768, 1,
                    0, 0, 0, 0, 0, 0, 1, 1, 1.f, false);
        launch_gemm(Q, Kb, ATTN, 0, 0, 0, 2048, 2048, 64, 768, 768, 2048, 1,
                    NI, 64, NI, 64, 12 * NN, NN, 12, 24, 0.125f, true);
        softmax_k<<<49152, 256>>>(ATTN, 2048);
        launch_gemm(ATTN, V, AO, 0, 0, 0, 2048, 64, 2048, 2048, 768, 768, 1,
                    12 * NN, NN, NI, 64, NI, 64, 12, 24, 1.f, false);
        launch_gemm(AO, wo1, Hbuf, 0, a1_bo + d * 768, Hbuf,
                    4096, 768, 768, 768, 768, 768, 1,
                    0, 0, 0, 0, 0, 0, 1, 1, 1.f, false);

        // ---- cross-attention ----
        layernorm_k<<<4096, 256>>>(Hbuf, Y, n2_s + d * 768, n2_b + d * 768);
        launch_gemm(Y, wq2, Q, 0, 0, 0, 4096, 768, 768, 768, 768, 768, 1,
                    0, 0, 0, 0, 0, 0, 1, 1, 1.f, false);
        launch_gemm(ctx, wk2, Kb, 0, 0, 0, 16, 768, 512, 512, 768, 768, 1,
                    16LL * 512, 0, 0, 0, 16LL * 768, 0, 1, 2, 1.f, false);
        launch_gemm(ctx, wv2, V, 0, 0, 0, 16, 768, 512, 512, 768, 768, 1,
                    16LL * 512, 0, 0, 0, 16LL * 768, 0, 1, 2, 1.f, false);
        launch_gemm(Q, Kb, ATTN, 0, 0, 0, 2048, 16, 64, 768, 768, 16, 1,
                    NI, 64, 16LL * 768, 64, 12LL * 2048 * 16, 2048LL * 16,
                    12, 24, 0.125f, true);
        softmax16_k<<<192, 256>>>(ATTN, 49152);
        launch_gemm(ATTN, V, AO, 0, 0, 0, 2048, 64, 16, 16, 768, 768, 1,
                    12LL * 2048 * 16, 2048LL * 16, 16LL * 768, 64, NI, 64,
                    12, 24, 1.f, false);
        launch_gemm(AO, wo2, Hbuf, 0, a2_bo + d * 768, Hbuf,
                    4096, 768, 768, 768, 768, 768, 1,
                    0, 0, 0, 0, 0, 0, 1, 1, 1.f, false);

        // ---- conv feed-forward (tensor cores) ----
        layernorm_bf_k<<<4096, 256>>>(Hbuf, FFINh, FFINl,
                                      n3_s + d * 768, n3_b + d * 768);
        wperm_k<<<4096, 256>>>(ff1_w + (size_t)d * 3072 * 768 * 9, Wth, Wtl,
                               3072, 768);
        convmma_k<1><<<dim3(32, 48, 2), 256>>>(FFINh, FFINl, Wth, Wtl,
                                               ff1_b + (size_t)d * 3072,
                                               768, 3072, FFh, FFl, 0, 0);
        wperm_k<<<4096, 256>>>(ff2_w + (size_t)d * 768 * 3072 * 9, Wth, Wtl,
                               768, 3072);
        convmma_k<0><<<dim3(32, 12, 2), 256>>>(FFh, FFl, Wth, Wtl,
                                               ff2_b + (size_t)d * 768,
                                               3072, 768, 0, 0, Hbuf, Hbuf);
    }

    launch_gemm(pout_w, Hbuf, out, pout_b, 0, x,
                768, 2048, 768, 768, 768, 2048, 1,
                0, 0, NI, 0, CT, 0, 1, 2, 1.f, true);
}